// round 11
// baseline (speedup 1.0000x reference)
#include <cuda_runtime.h>
#include <cuda_fp16.h>

#define N_NODES 10000
#define NB 32
#define SROW 2048            // halves per node row (state part)
#define SROWQ 256            // uint4 per row
#define NNZ_MAX 330000
#define XS_ELEMS (N_NODES * SROW)
#define S_STRIDE 640000      // N*NU per batch
#define XS_Q (XS_ELEMS / 8)

__device__ __half  g_XSh[XS_ELEMS];        // pass-1 gather source (state fp16), read-only
__device__ __half  g_XS2h[XS_ELEMS];       // pass-2 gather source (r*state fp16)
__device__ float2  g_XI[N_NODES * NB];     // inputs-part gather source
__device__ float2  g_YI[N_NODES * NB];     // inputs-part spmm result (pass1 computes, pass2 reads)
__device__ __half  g_Uh[NB * S_STRIDE];    // update gate
__device__ __half  g_wT1[128 * 88];        // w1^T fp16, n-major, K padded 66->80 (stride 88)
__device__ __half  g_wT2[64 * 88];         // w2^T likewise
__device__ int     g_cnt[N_NODES];         // zero-init (.bss); re-zeroed by k_rezero each call
__device__ int     g_cur[N_NODES];         // likewise
__device__ int     g_rowptr[N_NODES + 1];
__device__ int     g_col[NNZ_MAX];
__device__ float   g_val[NNZ_MAX];

// ---------- streams/events (static init; no device memory) ----------
static cudaStream_t g_s1;
static cudaEvent_t  g_evFork, g_evBuild, g_evCsr, g_evZ;
namespace {
struct HxInit {
    HxInit() {
        cudaStreamCreateWithFlags(&g_s1, cudaStreamNonBlocking);
        cudaEventCreateWithFlags(&g_evFork,  cudaEventDisableTiming);
        cudaEventCreateWithFlags(&g_evBuild, cudaEventDisableTiming);
        cudaEventCreateWithFlags(&g_evCsr,   cudaEventDisableTiming);
        cudaEventCreateWithFlags(&g_evZ,     cudaEventDisableTiming);
    }
};
static HxInit g_hxinit;
}

__device__ __forceinline__ float sigf(float x) { return 1.0f / (1.0f + __expf(-x)); }

__device__ __forceinline__ void mma16816(float* c, const unsigned* a, const unsigned* b) {
    asm volatile(
        "mma.sync.aligned.m16n8k16.row.col.f32.f16.f16.f32 "
        "{%0,%1,%2,%3}, {%4,%5,%6,%7}, {%8,%9}, {%0,%1,%2,%3};"
        : "+f"(c[0]), "+f"(c[1]), "+f"(c[2]), "+f"(c[3])
        : "r"(a[0]), "r"(a[1]), "r"(a[2]), "r"(a[3]), "r"(b[0]), "r"(b[1]));
}

// ---------------- CSR build ----------------
__global__ void k_hist(const int* __restrict__ rows, int nnz) {
    int i = blockIdx.x * blockDim.x + threadIdx.x;
    if (i < nnz) atomicAdd(&g_cnt[rows[i]], 1);
}
__global__ void k_scan() {   // 1024 threads, 2 barriers (warp-shuffle scan)
    __shared__ int wsum[32];
    int tid = threadIdx.x;
    int lane = tid & 31, wid = tid >> 5;
    int loc[10];
    int sum = 0;
#pragma unroll
    for (int k = 0; k < 10; k++) {
        int i = tid * 10 + k;
        int v = (i < N_NODES) ? g_cnt[i] : 0;
        loc[k] = v; sum += v;
    }
    int x = sum;
#pragma unroll
    for (int d = 1; d < 32; d <<= 1) {
        int y = __shfl_up_sync(0xffffffffu, x, d);
        if (lane >= d) x += y;
    }
    if (lane == 31) wsum[wid] = x;
    __syncthreads();
    if (wid == 0) {
        int y = wsum[lane];
#pragma unroll
        for (int d = 1; d < 32; d <<= 1) {
            int z = __shfl_up_sync(0xffffffffu, y, d);
            if (lane >= d) y += z;
        }
        wsum[lane] = y;
    }
    __syncthreads();
    int run = x - sum + (wid ? wsum[wid - 1] : 0);
#pragma unroll
    for (int k = 0; k < 10; k++) {
        int i = tid * 10 + k;
        if (i < N_NODES) g_rowptr[i] = run;
        run += loc[k];
    }
    if (tid == 1023) g_rowptr[N_NODES] = run;
}
__global__ void k_scatter(const int* __restrict__ rows, const int* __restrict__ cols,
                          const float* __restrict__ vals, int nnz) {
    int i = blockIdx.x * blockDim.x + threadIdx.x;
    if (i < nnz) {
        int r = rows[i];
        int p = g_rowptr[r] + atomicAdd(&g_cur[r], 1);
        g_col[p] = cols[i];
        g_val[p] = vals[i];
    }
}
// zero cnt/cur AFTER they are consumed, so the NEXT call (graph replay) starts clean.
__global__ void k_rezero() {
    int i = blockIdx.x * blockDim.x + threadIdx.x;
    if (i < N_NODES) { g_cnt[i] = 0; g_cur[i] = 0; }
}

// ---------------- weight transpose/pad (once, tiny) ----------------
__global__ void k_wprep(const float* __restrict__ w1, const float* __restrict__ w2) {
    int tid = blockIdx.x * 256 + threadIdx.x;
    if (tid < 128 * 88) {
        int n = tid / 88, k = tid - n * 88;
        g_wT1[tid] = __float2half((k < 66) ? w1[k * 128 + n] : 0.0f);
    } else if (tid < 128 * 88 + 64 * 88) {
        int j = tid - 128 * 88;
        int n = j / 88, k = j - n * 88;
        g_wT2[j] = __float2half((k < 66) ? w2[k * 64 + n] : 0.0f);
    }
}

// ---------------- fused builder (XS fp16 + XI) ----------------
__global__ void k_build(const float* __restrict__ inputs, const float* __restrict__ state) {
    int id = blockIdx.x * 256 + threadIdx.x;
    if (id < XS_Q) {
        int i8 = id * 8;
        int n = i8 >> 11;
        int b = (i8 >> 6) & 31;
        int u = i8 & 63;
        const float* sp = state + (size_t)b * S_STRIDE + n * 64 + u;
        float4 s0 = *(const float4*)sp;
        float4 s1 = *(const float4*)(sp + 4);
        uint4 o;
        ((__half2*)&o)[0] = __floats2half2_rn(s0.x, s0.y);
        ((__half2*)&o)[1] = __floats2half2_rn(s0.z, s0.w);
        ((__half2*)&o)[2] = __floats2half2_rn(s1.x, s1.y);
        ((__half2*)&o)[3] = __floats2half2_rn(s1.z, s1.w);
        ((uint4*)g_XSh)[id] = o;
    } else {
        int j = id - XS_Q;
        if (j < N_NODES * NB) {
            int b = j / N_NODES, n = j - b * N_NODES;
            float2 v = *(const float2*)&inputs[b * 20000 + 2 * n];
            g_XI[n * 32 + b] = v;
        }
    }
}

// ---------------- shared gather body ----------------
__device__ __forceinline__ void acc8(float* a, uint4 q, float v) {
    float2 f0 = __half22float2(*(__half2*)&q.x);
    float2 f1 = __half22float2(*(__half2*)&q.y);
    float2 f2 = __half22float2(*(__half2*)&q.z);
    float2 f3 = __half22float2(*(__half2*)&q.w);
    a[0] = fmaf(v, f0.x, a[0]); a[1] = fmaf(v, f0.y, a[1]);
    a[2] = fmaf(v, f1.x, a[2]); a[3] = fmaf(v, f1.y, a[3]);
    a[4] = fmaf(v, f2.x, a[4]); a[5] = fmaf(v, f2.y, a[5]);
    a[6] = fmaf(v, f3.x, a[6]); a[7] = fmaf(v, f3.y, a[7]);
}

// WITH_Y: the 16 owner lanes (slot%8==0) also accumulate the 2-wide inputs-part
// (predicated; adds ~6% L2 traffic, removes the separate k_spmm_in kernel).
template <bool WITH_Y>
__device__ __forceinline__ void gather_row(const uint4* __restrict__ X, int n, int slot,
                                           int t, int* scol, float* sval, float* a,
                                           float2& y, int brow, bool owner) {
    int beg = __ldg(&g_rowptr[n]), end = __ldg(&g_rowptr[n + 1]);
    for (int base = beg; base < end; base += 128) {
        int cnt = min(128, end - base);
        __syncthreads();
        if (t < cnt) { scol[t] = g_col[base + t]; sval[t] = g_val[base + t]; }
        __syncthreads();
        int e = 0;
        for (; e + 4 <= cnt; e += 4) {
            uint4 q0 = X[(size_t)scol[e + 0] * SROWQ + slot];
            uint4 q1 = X[(size_t)scol[e + 1] * SROWQ + slot];
            uint4 q2 = X[(size_t)scol[e + 2] * SROWQ + slot];
            uint4 q3 = X[(size_t)scol[e + 3] * SROWQ + slot];
            acc8(a, q0, sval[e + 0]);
            acc8(a, q1, sval[e + 1]);
            acc8(a, q2, sval[e + 2]);
            acc8(a, q3, sval[e + 3]);
            if (WITH_Y && owner) {
#pragma unroll
                for (int k = 0; k < 4; k++) {
                    float2 x = __ldg(&g_XI[scol[e + k] * 32 + brow]);
                    float v = sval[e + k];
                    y.x = fmaf(v, x.x, y.x);
                    y.y = fmaf(v, x.y, y.y);
                }
            }
        }
        for (; e < cnt; e++) {
            uint4 q = X[(size_t)scol[e] * SROWQ + slot];
            acc8(a, q, sval[e]);
            if (WITH_Y && owner) {
                float2 x = __ldg(&g_XI[scol[e] * 32 + brow]);
                float v = sval[e];
                y.x = fmaf(v, x.x, y.x);
                y.y = fmaf(v, x.y, y.y);
            }
        }
    }
}

// Stage this block's 16x(2+64) tile (+zero pad to K=80) into A[16][88].
__device__ __forceinline__ void stage_A(__half* A, int slot, const float* a, float2 y) {
    int row = (slot >> 3) & 15;
    int colb = 2 + (slot & 7) * 8;
#pragma unroll
    for (int i = 0; i < 4; i++) {
        __half2 hv = __floats2half2_rn(a[2 * i], a[2 * i + 1]);
        *(unsigned*)&A[row * 88 + colb + 2 * i] = *(unsigned*)&hv;
    }
    int r7 = slot & 7;
    if (r7 == 0) {
        __half2 hv = __floats2half2_rn(y.x, y.y);
        *(unsigned*)&A[row * 88] = *(unsigned*)&hv;
    } else if (r7 == 1) {
        unsigned* p = (unsigned*)&A[row * 88 + 66];
        p[0] = 0; p[1] = 0; p[2] = 0; p[3] = 0;      // halves 66..73
    } else if (r7 == 2) {
        unsigned* p = (unsigned*)&A[row * 88 + 74];
        p[0] = 0; p[1] = 0; p[2] = 0; p[3] = 0;      // halves 74..81 (79 is last read)
    }
}

// ---------------- pass 1: SpMM (+inline YI) + GEMM1 + sigmoid; r*state -> XS2h, u -> Uh ----------------
__global__ void __launch_bounds__(128, 8) k_spmm1f(const float* __restrict__ bias) {
    __shared__ int    scol[128];
    __shared__ float  sval[128];
    __shared__ __half A[16 * 88];
    int n = blockIdx.x >> 1;
    int h0 = blockIdx.x & 1;
    int tid = threadIdx.x;
    int slot = (h0 << 7) + tid;
    int brow = slot >> 3;                 // global batch 0..31
    bool owner = (slot & 7) == 0;
    float2 y = make_float2(0.f, 0.f);
    float a[8] = {0.f, 0.f, 0.f, 0.f, 0.f, 0.f, 0.f, 0.f};
    gather_row<true>((const uint4*)g_XSh, n, slot, tid, scol, sval, a, y, brow, owner);
    if (owner) g_YI[n * 32 + brow] = y;   // save for pass 2 (read after pass-1 kernel completes)
    stage_A(A, slot, a, y);
    __syncthreads();

    int lane = tid & 31, w = tid >> 5;
    int g = lane >> 2, tig = lane & 3;
    float acc[4][4] = {};
#pragma unroll
    for (int ks = 0; ks < 5; ks++) {
        int k0 = ks * 16 + 2 * tig;
        unsigned af[4];
        af[0] = *(const unsigned*)&A[g * 88 + k0];
        af[1] = *(const unsigned*)&A[(g + 8) * 88 + k0];
        af[2] = *(const unsigned*)&A[g * 88 + k0 + 8];
        af[3] = *(const unsigned*)&A[(g + 8) * 88 + k0 + 8];
#pragma unroll
        for (int nt = 0; nt < 4; nt++) {
            int nn = 32 * w + 8 * nt + g;
            unsigned bf[2];
            bf[0] = __ldg((const unsigned*)&g_wT1[nn * 88 + k0]);
            bf[1] = __ldg((const unsigned*)&g_wT1[nn * 88 + k0 + 8]);
            mma16816(acc[nt], af, bf);
        }
    }

    bool rside = (n < 5000);
#pragma unroll
    for (int nt = 0; nt < 4; nt++) {
        int j = 32 * w + 8 * nt + 2 * tig;         // output cols j, j+1
        float2 bb = *(const float2*)&bias[j];
#pragma unroll
        for (int h = 0; h < 2; h++) {
            int b = 16 * h0 + g + 8 * h;
            float v0 = sigf(acc[nt][2 * h]     + bb.x);
            float v1 = sigf(acc[nt][2 * h + 1] + bb.y);
            if (rside) {
                int t = 2 * n + (j >> 6);
                size_t off = (size_t)t * SROW + b * 64 + (j & 63);
                float2 s = __half22float2(*(const __half2*)&g_XSh[off]);
                __half2 hv = __floats2half2_rn(v0 * s.x, v1 * s.y);
                __stcs((unsigned*)&g_XS2h[off], *(unsigned*)&hv);
            } else {
                size_t off = (size_t)b * S_STRIDE + (n - 5000) * 128 + j;
                __half2 hv = __floats2half2_rn(v0, v1);
                __stcs((unsigned*)&g_Uh[off], *(unsigned*)&hv);
            }
        }
    }
}

// ---------------- pass 2: SpMM + GEMM2 + relu + GRU combine -> out ----------------
__global__ void __launch_bounds__(128, 8) k_spmm2f(const float* __restrict__ bias,
                                                   const float* __restrict__ state,
                                                   float* __restrict__ out) {
    __shared__ int    scol[128];
    __shared__ float  sval[128];
    __shared__ __half A[16 * 88];
    int n = blockIdx.x >> 1;
    int h0 = blockIdx.x & 1;
    int tid = threadIdx.x;
    int slot = (h0 << 7) + tid;
    int brow = slot >> 3;
    bool owner = (slot & 7) == 0;
    float2 y = make_float2(0.f, 0.f);
    float a[8] = {0.f, 0.f, 0.f, 0.f, 0.f, 0.f, 0.f, 0.f};
    gather_row<false>((const uint4*)g_XS2h, n, slot, tid, scol, sval, a, y, brow, owner);
    if (owner) y = g_YI[n * 32 + brow];   // inputs-part from pass 1
    stage_A(A, slot, a, y);
    __syncthreads();

    int lane = tid & 31, w = tid >> 5;
    int g = lane >> 2, tig = lane & 3;
    float acc[2][4] = {};
#pragma unroll
    for (int ks = 0; ks < 5; ks++) {
        int k0 = ks * 16 + 2 * tig;
        unsigned af[4];
        af[0] = *(const unsigned*)&A[g * 88 + k0];
        af[1] = *(const unsigned*)&A[(g + 8) * 88 + k0];
        af[2] = *(const unsigned*)&A[g * 88 + k0 + 8];
        af[3] = *(const unsigned*)&A[(g + 8) * 88 + k0 + 8];
#pragma unroll
        for (int nt = 0; nt < 2; nt++) {
            int nn = 16 * w + 8 * nt + g;
            unsigned bf[2];
            bf[0] = __ldg((const unsigned*)&g_wT2[nn * 88 + k0]);
            bf[1] = __ldg((const unsigned*)&g_wT2[nn * 88 + k0 + 8]);
            mma16816(acc[nt], af, bf);
        }
    }

#pragma unroll
    for (int nt = 0; nt < 2; nt++) {
        int j = 16 * w + 8 * nt + 2 * tig;         // cols j, j+1 (0..63)
        float2 bb = *(const float2*)&bias[j];
#pragma unroll
        for (int h = 0; h < 2; h++) {
            int b = 16 * h0 + g + 8 * h;
            float c0 = fmaxf(acc[nt][2 * h]     + bb.x, 0.0f);
            float c1 = fmaxf(acc[nt][2 * h + 1] + bb.y, 0.0f);
            size_t off = (size_t)b * S_STRIDE + n * 64 + j;
            unsigned uu = __ldcs((const unsigned*)&g_Uh[off]);
            float2 u = __half22float2(*(__half2*)&uu);
            float2 s = *(const float2*)&state[off];
            float2 o;
            o.x = u.x * s.x + (1.0f - u.x) * c0;
            o.y = u.y * s.y + (1.0f - u.y) * c1;
            *(float2*)&out[off] = o;
        }
    }
}

// ---------------- launch ----------------
extern "C" void kernel_launch(void* const* d_in, const int* in_sizes, int n_in,
                              void* d_out, int out_size) {
    const float* inputs = (const float*)d_in[0];
    const float* state  = (const float*)d_in[1];
    const int*   m_rows = (const int*)d_in[2];
    const int*   m_cols = (const int*)d_in[3];
    const float* m_vals = (const float*)d_in[4];
    const float* w1     = (const float*)d_in[5];
    const float* b1     = (const float*)d_in[6];
    const float* w2     = (const float*)d_in[7];
    const float* b2     = (const float*)d_in[8];
    float* out = (float*)d_out;
    int nnz = in_sizes[2];

    // side: weight prep + builder, parallel with CSR chain
    cudaEventRecord(g_evFork, 0);
    cudaStreamWaitEvent(g_s1, g_evFork, 0);
    k_wprep<<<66, 256, 0, g_s1>>>(w1, w2);
    k_build<<<(XS_Q + N_NODES * NB + 255) / 256, 256, 0, g_s1>>>(inputs, state);
    cudaEventRecord(g_evBuild, g_s1);

    // main: CSR chain (cnt/cur already zero: .bss init on first call, k_rezero on replays)
    k_hist<<<(nnz + 255) / 256, 256>>>(m_rows, nnz);
    k_scan<<<1, 1024>>>();
    k_scatter<<<(nnz + 255) / 256, 256>>>(m_rows, m_cols, m_vals, nnz);
    cudaEventRecord(g_evCsr, 0);

    // side: re-zero cnt/cur for the next call (after scan/scatter consumed them)
    cudaStreamWaitEvent(g_s1, g_evCsr, 0);
    k_rezero<<<(N_NODES + 255) / 256, 256, 0, g_s1>>>();
    cudaEventRecord(g_evZ, g_s1);

    // main: fused passes (need build + CSR only)
    cudaStreamWaitEvent(0, g_evBuild, 0);
    k_spmm1f<<<2 * N_NODES, 128>>>(b1);                 // XSh -> (XS2h, Uh, YI)
    k_spmm2f<<<2 * N_NODES, 128>>>(b2, state, out);     // XS2h -> out
    cudaStreamWaitEvent(0, g_evZ, 0);                   // join side stream into capture
}

// round 12
// speedup vs baseline: 1.0627x; 1.0627x over previous
#include <cuda_runtime.h>
#include <cuda_fp16.h>

#define N_NODES 10000
#define NB 32
#define SROW 2048            // halves per node row (state part)
#define SROWQ 256            // uint4 per row
#define NNZ_MAX 330000
#define XS_ELEMS (N_NODES * SROW)
#define S_STRIDE 640000      // N*NU per batch
#define XS_Q (XS_ELEMS / 8)

__device__ __half  g_XSh[XS_ELEMS];        // pass-1 gather source (state fp16), read-only
__device__ __half  g_XS2h[XS_ELEMS];       // pass-2 gather source (r*state fp16)
__device__ __half2 g_XIh[N_NODES * NB];    // inputs-part gather source (fp16)
__device__ float2  g_YI[N_NODES * NB];     // inputs-part spmm result (reused by both passes)
__device__ __half  g_Uh[NB * S_STRIDE];    // update gate
__device__ __half  g_wT1[128 * 88];        // w1^T fp16, n-major, K padded 66->80 (stride 88)
__device__ __half  g_wT2[64 * 88];         // w2^T likewise
__device__ int     g_cnt[12288];           // padded for int4 scan loads; .bss zero; re-zeroed each call
__device__ int     g_cur[N_NODES];         // likewise
__device__ int     g_rowptr[N_NODES + 1];
__device__ int     g_col[NNZ_MAX];
__device__ float   g_val[NNZ_MAX];

// ---------- streams/events (static init; no device memory) ----------
static cudaStream_t g_s1;
static cudaEvent_t  g_evFork, g_evCsr, g_evIn, g_evZ;
namespace {
struct HxInit {
    HxInit() {
        cudaStreamCreateWithFlags(&g_s1, cudaStreamNonBlocking);
        cudaEventCreateWithFlags(&g_evFork, cudaEventDisableTiming);
        cudaEventCreateWithFlags(&g_evCsr,  cudaEventDisableTiming);
        cudaEventCreateWithFlags(&g_evIn,   cudaEventDisableTiming);
        cudaEventCreateWithFlags(&g_evZ,    cudaEventDisableTiming);
    }
};
static HxInit g_hxinit;
}

__device__ __forceinline__ float sigf(float x) { return 1.0f / (1.0f + __expf(-x)); }

__device__ __forceinline__ void mma16816(float* c, const unsigned* a, const unsigned* b) {
    asm volatile(
        "mma.sync.aligned.m16n8k16.row.col.f32.f16.f16.f32 "
        "{%0,%1,%2,%3}, {%4,%5,%6,%7}, {%8,%9}, {%0,%1,%2,%3};"
        : "+f"(c[0]), "+f"(c[1]), "+f"(c[2]), "+f"(c[3])
        : "r"(a[0]), "r"(a[1]), "r"(a[2]), "r"(a[3]), "r"(b[0]), "r"(b[1]));
}

// ---------------- CSR build ----------------
__global__ void k_hist(const int* __restrict__ rows, int nnz) {
    int i = blockIdx.x * blockDim.x + threadIdx.x;
    if (i < nnz) atomicAdd(&g_cnt[rows[i]], 1);
}
// 1024 threads, 12 elems/thread via int4 loads (g_cnt padded to 12288, extras always 0)
__global__ void k_scan() {
    __shared__ int wsum[32];
    int tid = threadIdx.x;
    int lane = tid & 31, wid = tid >> 5;
    int4 v0 = ((const int4*)g_cnt)[tid * 3];
    int4 v1 = ((const int4*)g_cnt)[tid * 3 + 1];
    int4 v2 = ((const int4*)g_cnt)[tid * 3 + 2];
    int loc[12] = {v0.x, v0.y, v0.z, v0.w, v1.x, v1.y, v1.z, v1.w,
                   v2.x, v2.y, v2.z, v2.w};
    int sum = 0;
#pragma unroll
    for (int k = 0; k < 12; k++) sum += loc[k];
    int x = sum;
#pragma unroll
    for (int d = 1; d < 32; d <<= 1) {
        int y = __shfl_up_sync(0xffffffffu, x, d);
        if (lane >= d) x += y;
    }
    if (lane == 31) wsum[wid] = x;
    __syncthreads();
    if (wid == 0) {
        int y = wsum[lane];
#pragma unroll
        for (int d = 1; d < 32; d <<= 1) {
            int z = __shfl_up_sync(0xffffffffu, y, d);
            if (lane >= d) y += z;
        }
        wsum[lane] = y;
    }
    __syncthreads();
    int run = x - sum + (wid ? wsum[wid - 1] : 0);
    int i0 = tid * 12;
#pragma unroll
    for (int k = 0; k < 12; k++) {
        if (i0 + k <= N_NODES) g_rowptr[i0 + k] = run;
        run += loc[k];
    }
}
__global__ void k_scatter(const int* __restrict__ rows, const int* __restrict__ cols,
                          const float* __restrict__ vals, int nnz) {
    int i = blockIdx.x * blockDim.x + threadIdx.x;
    if (i < nnz) {
        int r = rows[i];
        int p = g_rowptr[r] + atomicAdd(&g_cur[r], 1);
        g_col[p] = cols[i];
        g_val[p] = vals[i];
    }
}
// zero cnt/cur AFTER they are consumed, so the NEXT call (graph replay) starts clean.
__global__ void k_rezero() {
    int i = blockIdx.x * blockDim.x + threadIdx.x;
    if (i < N_NODES) { g_cnt[i] = 0; g_cur[i] = 0; }
}

// ---------------- weight transpose/pad (once, tiny) ----------------
__global__ void k_wprep(const float* __restrict__ w1, const float* __restrict__ w2) {
    int tid = blockIdx.x * 256 + threadIdx.x;
    if (tid < 128 * 88) {
        int n = tid / 88, k = tid - n * 88;
        g_wT1[tid] = __float2half((k < 66) ? w1[k * 128 + n] : 0.0f);
    } else if (tid < 128 * 88 + 64 * 88) {
        int j = tid - 128 * 88;
        int n = j / 88, k = j - n * 88;
        g_wT2[j] = __float2half((k < 66) ? w2[k * 64 + n] : 0.0f);
    }
}

// ---------------- fused builder (XS fp16 + XI fp16) ----------------
__global__ void k_build(const float* __restrict__ inputs, const float* __restrict__ state) {
    int id = blockIdx.x * 256 + threadIdx.x;
    if (id < XS_Q) {
        int i8 = id * 8;
        int n = i8 >> 11;
        int b = (i8 >> 6) & 31;
        int u = i8 & 63;
        const float* sp = state + (size_t)b * S_STRIDE + n * 64 + u;
        float4 s0 = *(const float4*)sp;
        float4 s1 = *(const float4*)(sp + 4);
        uint4 o;
        ((__half2*)&o)[0] = __floats2half2_rn(s0.x, s0.y);
        ((__half2*)&o)[1] = __floats2half2_rn(s0.z, s0.w);
        ((__half2*)&o)[2] = __floats2half2_rn(s1.x, s1.y);
        ((__half2*)&o)[3] = __floats2half2_rn(s1.z, s1.w);
        ((uint4*)g_XSh)[id] = o;
    } else {
        int j = id - XS_Q;
        if (j < N_NODES * NB) {
            int b = j / N_NODES, n = j - b * N_NODES;
            float2 v = *(const float2*)&inputs[b * 20000 + 2 * n];
            g_XIh[n * 32 + b] = __floats2half2_rn(v.x, v.y);
        }
    }
}

// ---------------- SpMM (inputs part, once; fp16 gather) ----------------
__global__ void k_spmm_in() {
    int gw = (blockIdx.x * 256 + threadIdx.x) >> 5;
    int lane = threadIdx.x & 31;
    if (gw >= N_NODES) return;
    int beg = __ldg(&g_rowptr[gw]), end = __ldg(&g_rowptr[gw + 1]);
    float2 acc = make_float2(0.f, 0.f);
    for (int e = beg; e < end; e++) {
        int c = __ldg(&g_col[e]);
        float v = __ldg(&g_val[e]);
        float2 x = __half22float2(g_XIh[c * 32 + lane]);
        acc.x = fmaf(v, x.x, acc.x);
        acc.y = fmaf(v, x.y, acc.y);
    }
    g_YI[gw * 32 + lane] = acc;
}

// ---------------- shared gather body (UNTOUCHED hot loop) ----------------
__device__ __forceinline__ void acc8(float* a, uint4 q, float v) {
    float2 f0 = __half22float2(*(__half2*)&q.x);
    float2 f1 = __half22float2(*(__half2*)&q.y);
    float2 f2 = __half22float2(*(__half2*)&q.z);
    float2 f3 = __half22float2(*(__half2*)&q.w);
    a[0] = fmaf(v, f0.x, a[0]); a[1] = fmaf(v, f0.y, a[1]);
    a[2] = fmaf(v, f1.x, a[2]); a[3] = fmaf(v, f1.y, a[3]);
    a[4] = fmaf(v, f2.x, a[4]); a[5] = fmaf(v, f2.y, a[5]);
    a[6] = fmaf(v, f3.x, a[6]); a[7] = fmaf(v, f3.y, a[7]);
}

__device__ __forceinline__ void gather_row(const uint4* __restrict__ X, int n, int slot,
                                           int t, int* scol, float* sval, float* a) {
    int beg = __ldg(&g_rowptr[n]), end = __ldg(&g_rowptr[n + 1]);
    for (int base = beg; base < end; base += 128) {
        int cnt = min(128, end - base);
        __syncthreads();
        if (t < cnt) { scol[t] = g_col[base + t]; sval[t] = g_val[base + t]; }
        __syncthreads();
        int e = 0;
        for (; e + 4 <= cnt; e += 4) {
            uint4 q0 = X[(size_t)scol[e + 0] * SROWQ + slot];
            uint4 q1 = X[(size_t)scol[e + 1] * SROWQ + slot];
            uint4 q2 = X[(size_t)scol[e + 2] * SROWQ + slot];
            uint4 q3 = X[(size_t)scol[e + 3] * SROWQ + slot];
            acc8(a, q0, sval[e + 0]);
            acc8(a, q1, sval[e + 1]);
            acc8(a, q2, sval[e + 2]);
            acc8(a, q3, sval[e + 3]);
        }
        for (; e < cnt; e++) {
            uint4 q = X[(size_t)scol[e] * SROWQ + slot];
            acc8(a, q, sval[e]);
        }
    }
}

// Stage this block's 16x(2+64) tile (+zero pad to K=80) into A[16][88].
__device__ __forceinline__ void stage_A(__half* A, int n, int slot, const float* a) {
    int brow = slot >> 3;            // global batch 0..31
    int row = brow & 15;
    int colb = 2 + (slot & 7) * 8;
#pragma unroll
    for (int i = 0; i < 4; i++) {
        __half2 hv = __floats2half2_rn(a[2 * i], a[2 * i + 1]);
        *(unsigned*)&A[row * 88 + colb + 2 * i] = *(unsigned*)&hv;
    }
    int r7 = slot & 7;
    if (r7 == 0) {
        float2 y = g_YI[n * 32 + brow];
        __half2 hv = __floats2half2_rn(y.x, y.y);
        *(unsigned*)&A[row * 88] = *(unsigned*)&hv;
    } else if (r7 == 1) {
        unsigned* p = (unsigned*)&A[row * 88 + 66];
        p[0] = 0; p[1] = 0; p[2] = 0; p[3] = 0;      // halves 66..73
    } else if (r7 == 2) {
        unsigned* p = (unsigned*)&A[row * 88 + 74];
        p[0] = 0; p[1] = 0; p[2] = 0; p[3] = 0;      // halves 74..81 (79 is last read)
    }
}

// ---------------- pass 1: SpMM + GEMM1 + sigmoid; r*state -> XS2h, u -> Uh ----------------
__global__ void __launch_bounds__(128, 8) k_spmm1f(const float* __restrict__ bias) {
    __shared__ int    scol[128];
    __shared__ float  sval[128];
    __shared__ __half A[16 * 88];
    int n = blockIdx.x >> 1;
    int h0 = blockIdx.x & 1;
    int tid = threadIdx.x;
    int slot = (h0 << 7) + tid;
    float a[8] = {0.f, 0.f, 0.f, 0.f, 0.f, 0.f, 0.f, 0.f};
    gather_row((const uint4*)g_XSh, n, slot, tid, scol, sval, a);
    stage_A(A, n, slot, a);
    __syncthreads();

    int lane = tid & 31, w = tid >> 5;
    int g = lane >> 2, tig = lane & 3;
    float acc[4][4] = {};
#pragma unroll
    for (int ks = 0; ks < 5; ks++) {
        int k0 = ks * 16 + 2 * tig;
        unsigned af[4];
        af[0] = *(const unsigned*)&A[g * 88 + k0];
        af[1] = *(const unsigned*)&A[(g + 8) * 88 + k0];
        af[2] = *(const unsigned*)&A[g * 88 + k0 + 8];
        af[3] = *(const unsigned*)&A[(g + 8) * 88 + k0 + 8];
#pragma unroll
        for (int nt = 0; nt < 4; nt++) {
            int nn = 32 * w + 8 * nt + g;
            unsigned bf[2];
            bf[0] = __ldg((const unsigned*)&g_wT1[nn * 88 + k0]);
            bf[1] = __ldg((const unsigned*)&g_wT1[nn * 88 + k0 + 8]);
            mma16816(acc[nt], af, bf);
        }
    }

    bool rside = (n < 5000);
#pragma unroll
    for (int nt = 0; nt < 4; nt++) {
        int j = 32 * w + 8 * nt + 2 * tig;         // output cols j, j+1
        float2 bb = *(const float2*)&bias[j];
#pragma unroll
        for (int h = 0; h < 2; h++) {
            int b = 16 * h0 + g + 8 * h;
            float v0 = sigf(acc[nt][2 * h]     + bb.x);
            float v1 = sigf(acc[nt][2 * h + 1] + bb.y);
            if (rside) {
                int t = 2 * n + (j >> 6);
                size_t off = (size_t)t * SROW + b * 64 + (j & 63);
                float2 s = __half22float2(*(const __half2*)&g_XSh[off]);
                __half2 hv = __floats2half2_rn(v0 * s.x, v1 * s.y);
                __stcs((unsigned*)&g_XS2h[off], *(unsigned*)&hv);
            } else {
                size_t off = (size_t)b * S_STRIDE + (n - 5000) * 128 + j;
                __half2 hv = __floats2half2_rn(v0, v1);
                __stcs((unsigned*)&g_Uh[off], *(unsigned*)&hv);
            }
        }
    }
}

// ---------------- pass 2: SpMM + GEMM2 + relu + GRU combine -> out ----------------
__global__ void __launch_bounds__(128, 8) k_spmm2f(const float* __restrict__ bias,
                                                   const float* __restrict__ state,
                                                   float* __restrict__ out) {
    __shared__ int    scol[128];
    __shared__ float  sval[128];
    __shared__ __half A[16 * 88];
    int n = blockIdx.x >> 1;
    int h0 = blockIdx.x & 1;
    int tid = threadIdx.x;
    int slot = (h0 << 7) + tid;
    float a[8] = {0.f, 0.f, 0.f, 0.f, 0.f, 0.f, 0.f, 0.f};
    gather_row((const uint4*)g_XS2h, n, slot, tid, scol, sval, a);
    stage_A(A, n, slot, a);
    __syncthreads();

    int lane = tid & 31, w = tid >> 5;
    int g = lane >> 2, tig = lane & 3;
    float acc[2][4] = {};
#pragma unroll
    for (int ks = 0; ks < 5; ks++) {
        int k0 = ks * 16 + 2 * tig;
        unsigned af[4];
        af[0] = *(const unsigned*)&A[g * 88 + k0];
        af[1] = *(const unsigned*)&A[(g + 8) * 88 + k0];
        af[2] = *(const unsigned*)&A[g * 88 + k0 + 8];
        af[3] = *(const unsigned*)&A[(g + 8) * 88 + k0 + 8];
#pragma unroll
        for (int nt = 0; nt < 2; nt++) {
            int nn = 16 * w + 8 * nt + g;
            unsigned bf[2];
            bf[0] = __ldg((const unsigned*)&g_wT2[nn * 88 + k0]);
            bf[1] = __ldg((const unsigned*)&g_wT2[nn * 88 + k0 + 8]);
            mma16816(acc[nt], af, bf);
        }
    }

#pragma unroll
    for (int nt = 0; nt < 2; nt++) {
        int j = 16 * w + 8 * nt + 2 * tig;         // cols j, j+1 (0..63)
        float2 bb = *(const float2*)&bias[j];
#pragma unroll
        for (int h = 0; h < 2; h++) {
            int b = 16 * h0 + g + 8 * h;
            float c0 = fmaxf(acc[nt][2 * h]     + bb.x, 0.0f);
            float c1 = fmaxf(acc[nt][2 * h + 1] + bb.y, 0.0f);
            size_t off = (size_t)b * S_STRIDE + n * 64 + j;
            unsigned uu = __ldcs((const unsigned*)&g_Uh[off]);
            float2 u = __half22float2(*(__half2*)&uu);
            float2 s = *(const float2*)&state[off];
            float2 o;
            o.x = u.x * s.x + (1.0f - u.x) * c0;
            o.y = u.y * s.y + (1.0f - u.y) * c1;
            *(float2*)&out[off] = o;
        }
    }
}

// ---------------- launch ----------------
extern "C" void kernel_launch(void* const* d_in, const int* in_sizes, int n_in,
                              void* d_out, int out_size) {
    const float* inputs = (const float*)d_in[0];
    const float* state  = (const float*)d_in[1];
    const int*   m_rows = (const int*)d_in[2];
    const int*   m_cols = (const int*)d_in[3];
    const float* m_vals = (const float*)d_in[4];
    const float* w1     = (const float*)d_in[5];
    const float* b1     = (const float*)d_in[6];
    const float* w2     = (const float*)d_in[7];
    const float* b2     = (const float*)d_in[8];
    float* out = (float*)d_out;
    int nnz = in_sizes[2];

    // side: weight prep + builder, parallel with CSR chain
    cudaEventRecord(g_evFork, 0);
    cudaStreamWaitEvent(g_s1, g_evFork, 0);
    k_wprep<<<66, 256, 0, g_s1>>>(w1, w2);
    k_build<<<(XS_Q + N_NODES * NB + 255) / 256, 256, 0, g_s1>>>(inputs, state);

    // main: CSR chain (cnt/cur already zero: .bss on first call, k_rezero on prior call)
    k_hist<<<(nnz + 255) / 256, 256>>>(m_rows, nnz);
    k_scan<<<1, 1024>>>();
    k_scatter<<<(nnz + 255) / 256, 256>>>(m_rows, m_cols, m_vals, nnz);
    cudaEventRecord(g_evCsr, 0);

    // side: inputs-part SpMM (needs CSR; wprep/build ordered before it on g_s1),
    // then re-zero cnt/cur for the next call
    cudaStreamWaitEvent(g_s1, g_evCsr, 0);
    k_spmm_in<<<(N_NODES * NB + 255) / 256, 256, 0, g_s1>>>();
    cudaEventRecord(g_evIn, g_s1);
    k_rezero<<<(N_NODES + 255) / 256, 256, 0, g_s1>>>();
    cudaEventRecord(g_evZ, g_s1);

    // main: fused passes (evIn implies wprep+build+CSR+YI all complete)
    cudaStreamWaitEvent(0, g_evIn, 0);
    k_spmm1f<<<2 * N_NODES, 128>>>(b1);                 // XSh -> (XS2h, Uh)
    k_spmm2f<<<2 * N_NODES, 128>>>(b2, state, out);     // XS2h -> out
    cudaStreamWaitEvent(0, g_evZ, 0);                   // join side stream into capture
}

// round 13
// speedup vs baseline: 1.0714x; 1.0082x over previous
#include <cuda_runtime.h>
#include <cuda_fp16.h>

#define N_NODES 10000
#define NB 32
#define SROW 2048            // halves per node row (state part)
#define SROWQ 256            // uint4 per row
#define CAP 128              // bucket capacity per row (max row len ~55; P(>=96)~1e-18)
#define XS_ELEMS (N_NODES * SROW)
#define S_STRIDE 640000      // N*NU per batch
#define XS_Q (XS_ELEMS / 8)

__device__ __half  g_XSh[XS_ELEMS];        // pass-1 gather source (state fp16), read-only
__device__ __half  g_XS2h[XS_ELEMS];       // pass-2 gather source (r*state fp16)
__device__ __half2 g_XIh[N_NODES * NB];    // inputs-part gather source (fp16)
__device__ float2  g_YI[N_NODES * NB];     // inputs-part spmm result (pass1 writes, pass2 reads)
__device__ __half  g_Uh[NB * S_STRIDE];    // update gate
__device__ __half  g_wT1[128 * 88];        // w1^T fp16, n-major, K padded 66->80 (stride 88)
__device__ __half  g_wT2[64 * 88];         // w2^T likewise
__device__ int     g_cnt[N_NODES];         // .bss zero on load; zeroed by pass2 for next replay
__device__ int     g_len[N_NODES];         // row length snapshot (pass1 writes, pass2 reads)
__device__ int     g_colB[N_NODES * CAP];  // bucket CSR cols
__device__ float   g_valB[N_NODES * CAP];  // bucket CSR vals

// ---------- streams/events (static init; no device memory) ----------
static cudaStream_t g_s1;
static cudaEvent_t  g_evFork, g_evBuild;
namespace {
struct HxInit {
    HxInit() {
        cudaStreamCreateWithFlags(&g_s1, cudaStreamNonBlocking);
        cudaEventCreateWithFlags(&g_evFork,  cudaEventDisableTiming);
        cudaEventCreateWithFlags(&g_evBuild, cudaEventDisableTiming);
    }
};
static HxInit g_hxinit;
}

__device__ __forceinline__ float sigf(float x) { return 1.0f / (1.0f + __expf(-x)); }

__device__ __forceinline__ void mma16816(float* c, const unsigned* a, const unsigned* b) {
    asm volatile(
        "mma.sync.aligned.m16n8k16.row.col.f32.f16.f16.f32 "
        "{%0,%1,%2,%3}, {%4,%5,%6,%7}, {%8,%9}, {%0,%1,%2,%3};"
        : "+f"(c[0]), "+f"(c[1]), "+f"(c[2]), "+f"(c[3])
        : "r"(a[0]), "r"(a[1]), "r"(a[2]), "r"(a[3]), "r"(b[0]), "r"(b[1]));
}

// ---------------- bucket CSR scatter (no hist/scan needed) ----------------
__global__ void k_scatter(const int* __restrict__ rows, const int* __restrict__ cols,
                          const float* __restrict__ vals, int nnz) {
    int i = blockIdx.x * blockDim.x + threadIdx.x;
    if (i < nnz) {
        int r = rows[i];
        int p = atomicAdd(&g_cnt[r], 1);
        if (p < CAP) {
            g_colB[(r << 7) + p] = cols[i];
            g_valB[(r << 7) + p] = vals[i];
        }
    }
}

// ---------------- weight transpose/pad (once, tiny) ----------------
__global__ void k_wprep(const float* __restrict__ w1, const float* __restrict__ w2) {
    int tid = blockIdx.x * 256 + threadIdx.x;
    if (tid < 128 * 88) {
        int n = tid / 88, k = tid - n * 88;
        g_wT1[tid] = __float2half((k < 66) ? w1[k * 128 + n] : 0.0f);
    } else if (tid < 128 * 88 + 64 * 88) {
        int j = tid - 128 * 88;
        int n = j / 88, k = j - n * 88;
        g_wT2[j] = __float2half((k < 66) ? w2[k * 64 + n] : 0.0f);
    }
}

// ---------------- fused builder (XS fp16 + XI fp16) ----------------
__global__ void k_build(const float* __restrict__ inputs, const float* __restrict__ state) {
    int id = blockIdx.x * 256 + threadIdx.x;
    if (id < XS_Q) {
        int i8 = id * 8;
        int n = i8 >> 11;
        int b = (i8 >> 6) & 31;
        int u = i8 & 63;
        const float* sp = state + (size_t)b * S_STRIDE + n * 64 + u;
        float4 s0 = *(const float4*)sp;
        float4 s1 = *(const float4*)(sp + 4);
        uint4 o;
        ((__half2*)&o)[0] = __floats2half2_rn(s0.x, s0.y);
        ((__half2*)&o)[1] = __floats2half2_rn(s0.z, s0.w);
        ((__half2*)&o)[2] = __floats2half2_rn(s1.x, s1.y);
        ((__half2*)&o)[3] = __floats2half2_rn(s1.z, s1.w);
        ((uint4*)g_XSh)[id] = o;
    } else {
        int j = id - XS_Q;
        if (j < N_NODES * NB) {
            int b = j / N_NODES, n = j - b * N_NODES;
            float2 v = *(const float2*)&inputs[b * 20000 + 2 * n];
            g_XIh[n * 32 + b] = __floats2half2_rn(v.x, v.y);
        }
    }
}

// ---------------- shared gather body (single tile, cnt <= 128) ----------------
__device__ __forceinline__ void acc8(float* a, uint4 q, float v) {
    float2 f0 = __half22float2(*(__half2*)&q.x);
    float2 f1 = __half22float2(*(__half2*)&q.y);
    float2 f2 = __half22float2(*(__half2*)&q.z);
    float2 f3 = __half22float2(*(__half2*)&q.w);
    a[0] = fmaf(v, f0.x, a[0]); a[1] = fmaf(v, f0.y, a[1]);
    a[2] = fmaf(v, f1.x, a[2]); a[3] = fmaf(v, f1.y, a[3]);
    a[4] = fmaf(v, f2.x, a[4]); a[5] = fmaf(v, f2.y, a[5]);
    a[6] = fmaf(v, f3.x, a[6]); a[7] = fmaf(v, f3.y, a[7]);
}

__device__ __forceinline__ void gather_row(const uint4* __restrict__ X, int slot,
                                           const int* scol, const float* sval,
                                           int cnt, float* a) {
    int e = 0;
    for (; e + 4 <= cnt; e += 4) {
        uint4 q0 = X[(size_t)scol[e + 0] * SROWQ + slot];
        uint4 q1 = X[(size_t)scol[e + 1] * SROWQ + slot];
        uint4 q2 = X[(size_t)scol[e + 2] * SROWQ + slot];
        uint4 q3 = X[(size_t)scol[e + 3] * SROWQ + slot];
        acc8(a, q0, sval[e + 0]);
        acc8(a, q1, sval[e + 1]);
        acc8(a, q2, sval[e + 2]);
        acc8(a, q3, sval[e + 3]);
    }
    for (; e < cnt; e++) {
        uint4 q = X[(size_t)scol[e] * SROWQ + slot];
        acc8(a, q, sval[e]);
    }
}

// Stage this block's 16x(2+64) tile (+zero pad to K=80) into A[16][88].
// y is only meaningful on owner lanes (slot%8==0).
__device__ __forceinline__ void stage_A(__half* A, int slot, const float* a, float2 y) {
    int row = (slot >> 3) & 15;
    int colb = 2 + (slot & 7) * 8;
#pragma unroll
    for (int i = 0; i < 4; i++) {
        __half2 hv = __floats2half2_rn(a[2 * i], a[2 * i + 1]);
        *(unsigned*)&A[row * 88 + colb + 2 * i] = *(unsigned*)&hv;
    }
    int r7 = slot & 7;
    if (r7 == 0) {
        __half2 hv = __floats2half2_rn(y.x, y.y);
        *(unsigned*)&A[row * 88] = *(unsigned*)&hv;
    } else if (r7 == 1) {
        unsigned* p = (unsigned*)&A[row * 88 + 66];
        p[0] = 0; p[1] = 0; p[2] = 0; p[3] = 0;      // halves 66..73
    } else if (r7 == 2) {
        unsigned* p = (unsigned*)&A[row * 88 + 74];
        p[0] = 0; p[1] = 0; p[2] = 0; p[3] = 0;      // halves 74..81 (79 is last read)
    }
}

// ---------------- pass 1: SpMM + owner-lane YI + GEMM1 + sigmoid ----------------
__global__ void __launch_bounds__(128, 8) k_spmm1f(const float* __restrict__ bias) {
    __shared__ int    scol[128];
    __shared__ float  sval[128];
    __shared__ __half A[16 * 88];
    int n = blockIdx.x >> 1;
    int h0 = blockIdx.x & 1;
    int tid = threadIdx.x;
    int slot = (h0 << 7) + tid;
    int cnt = __ldg(&g_cnt[n]);
    if (tid == 0 && h0 == 0) g_len[n] = cnt;     // snapshot for pass 2
    if (tid < cnt) { scol[tid] = g_colB[(n << 7) + tid]; sval[tid] = g_valB[(n << 7) + tid]; }
    __syncthreads();

    float a[8] = {0.f, 0.f, 0.f, 0.f, 0.f, 0.f, 0.f, 0.f};
    gather_row((const uint4*)g_XSh, slot, scol, sval, cnt, a);

    // owner lanes: inputs-part SpMM from staged edge list (post-loop, not in hot loop)
    float2 y = make_float2(0.f, 0.f);
    int brow = slot >> 3;
    if ((slot & 7) == 0) {
        int e = 0;
        for (; e + 4 <= cnt; e += 4) {
            float2 x0 = __half22float2(g_XIh[scol[e + 0] * 32 + brow]);
            float2 x1 = __half22float2(g_XIh[scol[e + 1] * 32 + brow]);
            float2 x2 = __half22float2(g_XIh[scol[e + 2] * 32 + brow]);
            float2 x3 = __half22float2(g_XIh[scol[e + 3] * 32 + brow]);
            y.x = fmaf(sval[e + 0], x0.x, y.x); y.y = fmaf(sval[e + 0], x0.y, y.y);
            y.x = fmaf(sval[e + 1], x1.x, y.x); y.y = fmaf(sval[e + 1], x1.y, y.y);
            y.x = fmaf(sval[e + 2], x2.x, y.x); y.y = fmaf(sval[e + 2], x2.y, y.y);
            y.x = fmaf(sval[e + 3], x3.x, y.x); y.y = fmaf(sval[e + 3], x3.y, y.y);
        }
        for (; e < cnt; e++) {
            float2 x = __half22float2(g_XIh[scol[e] * 32 + brow]);
            y.x = fmaf(sval[e], x.x, y.x);
            y.y = fmaf(sval[e], x.y, y.y);
        }
        g_YI[n * 32 + brow] = y;                 // for pass 2
    }
    stage_A(A, slot, a, y);
    __syncthreads();

    int lane = tid & 31, w = tid >> 5;
    int g = lane >> 2, tig = lane & 3;
    float acc[4][4] = {};
#pragma unroll
    for (int ks = 0; ks < 5; ks++) {
        int k0 = ks * 16 + 2 * tig;
        unsigned af[4];
        af[0] = *(const unsigned*)&A[g * 88 + k0];
        af[1] = *(const unsigned*)&A[(g + 8) * 88 + k0];
        af[2] = *(const unsigned*)&A[g * 88 + k0 + 8];
        af[3] = *(const unsigned*)&A[(g + 8) * 88 + k0 + 8];
#pragma unroll
        for (int nt = 0; nt < 4; nt++) {
            int nn = 32 * w + 8 * nt + g;
            unsigned bf[2];
            bf[0] = __ldg((const unsigned*)&g_wT1[nn * 88 + k0]);
            bf[1] = __ldg((const unsigned*)&g_wT1[nn * 88 + k0 + 8]);
            mma16816(acc[nt], af, bf);
        }
    }

    bool rside = (n < 5000);
#pragma unroll
    for (int nt = 0; nt < 4; nt++) {
        int j = 32 * w + 8 * nt + 2 * tig;         // output cols j, j+1
        float2 bb = *(const float2*)&bias[j];
#pragma unroll
        for (int h = 0; h < 2; h++) {
            int b = 16 * h0 + g + 8 * h;
            float v0 = sigf(acc[nt][2 * h]     + bb.x);
            float v1 = sigf(acc[nt][2 * h + 1] + bb.y);
            if (rside) {
                int t = 2 * n + (j >> 6);
                size_t off = (size_t)t * SROW + b * 64 + (j & 63);
                float2 s = __half22float2(*(const __half2*)&g_XSh[off]);
                __half2 hv = __floats2half2_rn(v0 * s.x, v1 * s.y);
                __stcs((unsigned*)&g_XS2h[off], *(unsigned*)&hv);
            } else {
                size_t off = (size_t)b * S_STRIDE + (n - 5000) * 128 + j;
                __half2 hv = __floats2half2_rn(v0, v1);
                __stcs((unsigned*)&g_Uh[off], *(unsigned*)&hv);
            }
        }
    }
}

// ---------------- pass 2: SpMM + GEMM2 + relu + GRU combine -> out ----------------
__global__ void __launch_bounds__(128, 8) k_spmm2f(const float* __restrict__ bias,
                                                   const float* __restrict__ state,
                                                   float* __restrict__ out) {
    __shared__ int    scol[128];
    __shared__ float  sval[128];
    __shared__ __half A[16 * 88];
    int n = blockIdx.x >> 1;
    int h0 = blockIdx.x & 1;
    int tid = threadIdx.x;
    int slot = (h0 << 7) + tid;
    int cnt = __ldg(&g_len[n]);
    if (tid == 0 && h0 == 0) g_cnt[n] = 0;       // clean for next replay's scatter
    if (tid < cnt) { scol[tid] = g_colB[(n << 7) + tid]; sval[tid] = g_valB[(n << 7) + tid]; }
    __syncthreads();

    float a[8] = {0.f, 0.f, 0.f, 0.f, 0.f, 0.f, 0.f, 0.f};
    gather_row((const uint4*)g_XS2h, slot, scol, sval, cnt, a);

    float2 y = make_float2(0.f, 0.f);
    int brow = slot >> 3;
    if ((slot & 7) == 0) y = g_YI[n * 32 + brow];    // inputs-part from pass 1
    stage_A(A, slot, a, y);
    __syncthreads();

    int lane = tid & 31, w = tid >> 5;
    int g = lane >> 2, tig = lane & 3;
    float acc[2][4] = {};
#pragma unroll
    for (int ks = 0; ks < 5; ks++) {
        int k0 = ks * 16 + 2 * tig;
        unsigned af[4];
        af[0] = *(const unsigned*)&A[g * 88 + k0];
        af[1] = *(const unsigned*)&A[(g + 8) * 88 + k0];
        af[2] = *(const unsigned*)&A[g * 88 + k0 + 8];
        af[3] = *(const unsigned*)&A[(g + 8) * 88 + k0 + 8];
#pragma unroll
        for (int nt = 0; nt < 2; nt++) {
            int nn = 16 * w + 8 * nt + g;
            unsigned bf[2];
            bf[0] = __ldg((const unsigned*)&g_wT2[nn * 88 + k0]);
            bf[1] = __ldg((const unsigned*)&g_wT2[nn * 88 + k0 + 8]);
            mma16816(acc[nt], af, bf);
        }
    }

#pragma unroll
    for (int nt = 0; nt < 2; nt++) {
        int j = 16 * w + 8 * nt + 2 * tig;         // cols j, j+1 (0..63)
        float2 bb = *(const float2*)&bias[j];
#pragma unroll
        for (int h = 0; h < 2; h++) {
            int b = 16 * h0 + g + 8 * h;
            float c0 = fmaxf(acc[nt][2 * h]     + bb.x, 0.0f);
            float c1 = fmaxf(acc[nt][2 * h + 1] + bb.y, 0.0f);
            size_t off = (size_t)b * S_STRIDE + n * 64 + j;
            unsigned uu = __ldcs((const unsigned*)&g_Uh[off]);
            float2 u = __half22float2(*(__half2*)&uu);
            float2 s = *(const float2*)&state[off];
            float2 o;
            o.x = u.x * s.x + (1.0f - u.x) * c0;
            o.y = u.y * s.y + (1.0f - u.y) * c1;
            *(float2*)&out[off] = o;
        }
    }
}

// ---------------- launch ----------------
extern "C" void kernel_launch(void* const* d_in, const int* in_sizes, int n_in,
                              void* d_out, int out_size) {
    const float* inputs = (const float*)d_in[0];
    const float* state  = (const float*)d_in[1];
    const int*   m_rows = (const int*)d_in[2];
    const int*   m_cols = (const int*)d_in[3];
    const float* m_vals = (const float*)d_in[4];
    const float* w1     = (const float*)d_in[5];
    const float* b1     = (const float*)d_in[6];
    const float* w2     = (const float*)d_in[7];
    const float* b2     = (const float*)d_in[8];
    float* out = (float*)d_out;
    int nnz = in_sizes[2];

    // side: weight prep + builder, parallel with scatter
    cudaEventRecord(g_evFork, 0);
    cudaStreamWaitEvent(g_s1, g_evFork, 0);
    k_wprep<<<66, 256, 0, g_s1>>>(w1, w2);
    k_build<<<(XS_Q + N_NODES * NB + 255) / 256, 256, 0, g_s1>>>(inputs, state);
    cudaEventRecord(g_evBuild, g_s1);

    // main: bucket scatter (g_cnt is zero: .bss on first call, pass2 zeroed it last call)
    k_scatter<<<(nnz + 255) / 256, 256>>>(m_rows, m_cols, m_vals, nnz);

    // main: fused passes (need scatter [in-order] + build/wprep [event])
    cudaStreamWaitEvent(0, g_evBuild, 0);
    k_spmm1f<<<2 * N_NODES, 128>>>(b1);                 // XSh -> (XS2h, Uh, YI, len)
    k_spmm2f<<<2 * N_NODES, 128>>>(b2, state, out);     // XS2h -> out; zeroes cnt
}

// round 14
// speedup vs baseline: 1.0826x; 1.0104x over previous
#include <cuda_runtime.h>
#include <cuda_fp16.h>

#define N_NODES 10000
#define NB 32
#define SROW 2048            // halves per node row (state part)
#define SROWQ 256            // uint4 per row
#define CAP 128              // bucket capacity per row (max row len ~55; P(>=96)~1e-18)
#define XS_ELEMS (N_NODES * SROW)
#define S_STRIDE 640000      // N*NU per batch
#define XS_Q (XS_ELEMS / 8)

__device__ __half  g_XSh[XS_ELEMS];        // pass-1 gather source (state fp16), read-only
__device__ __half  g_XS2h[XS_ELEMS];       // pass-2 gather source (r*state fp16)
__device__ __half2 g_XIh[N_NODES * NB];    // inputs-part gather source (fp16)
__device__ float2  g_YI[N_NODES * NB];     // inputs-part spmm result (pass1 writes, pass2 reads)
__device__ __half  g_Uh[NB * S_STRIDE];    // update gate
__device__ __half  g_wT1[128 * 88];        // w1^T fp16, n-major, K padded 66->80 (stride 88)
__device__ __half  g_wT2[64 * 88];         // w2^T likewise
__device__ int     g_cnt[N_NODES];         // .bss zero on load; zeroed by pass2 for next replay
__device__ int     g_len[N_NODES];         // row length snapshot (pass1 writes, pass2 reads)
__device__ int2    g_eB[N_NODES * CAP];    // packed edges: {col<<8, val bits}

// ---------- streams/events (static init; no device memory) ----------
static cudaStream_t g_s1;
static cudaEvent_t  g_evFork, g_evBuild;
namespace {
struct HxInit {
    HxInit() {
        cudaStreamCreateWithFlags(&g_s1, cudaStreamNonBlocking);
        cudaEventCreateWithFlags(&g_evFork,  cudaEventDisableTiming);
        cudaEventCreateWithFlags(&g_evBuild, cudaEventDisableTiming);
    }
};
static HxInit g_hxinit;
}

__device__ __forceinline__ float sigf(float x) { return 1.0f / (1.0f + __expf(-x)); }

__device__ __forceinline__ void mma16816(float* c, const unsigned* a, const unsigned* b) {
    asm volatile(
        "mma.sync.aligned.m16n8k16.row.col.f32.f16.f16.f32 "
        "{%0,%1,%2,%3}, {%4,%5,%6,%7}, {%8,%9}, {%0,%1,%2,%3};"
        : "+f"(c[0]), "+f"(c[1]), "+f"(c[2]), "+f"(c[3])
        : "r"(a[0]), "r"(a[1]), "r"(a[2]), "r"(a[3]), "r"(b[0]), "r"(b[1]));
}

// ---------------- bucket scatter (packed edges, no hist/scan) ----------------
__global__ void k_scatter(const int* __restrict__ rows, const int* __restrict__ cols,
                          const float* __restrict__ vals, int nnz) {
    int i = blockIdx.x * blockDim.x + threadIdx.x;
    if (i < nnz) {
        int r = rows[i];
        int p = atomicAdd(&g_cnt[r], 1);
        if (p < CAP)
            g_eB[(r << 7) + p] = make_int2(cols[i] << 8, __float_as_int(vals[i]));
    }
}

// ---------------- weight transpose/pad (once, tiny) ----------------
__global__ void k_wprep(const float* __restrict__ w1, const float* __restrict__ w2) {
    int tid = blockIdx.x * 256 + threadIdx.x;
    if (tid < 128 * 88) {
        int n = tid / 88, k = tid - n * 88;
        g_wT1[tid] = __float2half((k < 66) ? w1[k * 128 + n] : 0.0f);
    } else if (tid < 128 * 88 + 64 * 88) {
        int j = tid - 128 * 88;
        int n = j / 88, k = j - n * 88;
        g_wT2[j] = __float2half((k < 66) ? w2[k * 64 + n] : 0.0f);
    }
}

// ---------------- fused builder (XS fp16 + XI fp16) ----------------
__global__ void k_build(const float* __restrict__ inputs, const float* __restrict__ state) {
    int id = blockIdx.x * 256 + threadIdx.x;
    if (id < XS_Q) {
        int i8 = id * 8;
        int n = i8 >> 11;
        int b = (i8 >> 6) & 31;
        int u = i8 & 63;
        const float* sp = state + (size_t)b * S_STRIDE + n * 64 + u;
        float4 s0 = *(const float4*)sp;
        float4 s1 = *(const float4*)(sp + 4);
        uint4 o;
        ((__half2*)&o)[0] = __floats2half2_rn(s0.x, s0.y);
        ((__half2*)&o)[1] = __floats2half2_rn(s0.z, s0.w);
        ((__half2*)&o)[2] = __floats2half2_rn(s1.x, s1.y);
        ((__half2*)&o)[3] = __floats2half2_rn(s1.z, s1.w);
        ((uint4*)g_XSh)[id] = o;
    } else {
        int j = id - XS_Q;
        if (j < N_NODES * NB) {
            int b = j / N_NODES, n = j - b * N_NODES;
            float2 v = *(const float2*)&inputs[b * 20000 + 2 * n];
            g_XIh[n * 32 + b] = __floats2half2_rn(v.x, v.y);
        }
    }
}

// ---------------- shared gather body (packed edges, cnt <= 128) ----------------
__device__ __forceinline__ void acc8(float* a, uint4 q, float v) {
    float2 f0 = __half22float2(*(__half2*)&q.x);
    float2 f1 = __half22float2(*(__half2*)&q.y);
    float2 f2 = __half22float2(*(__half2*)&q.z);
    float2 f3 = __half22float2(*(__half2*)&q.w);
    a[0] = fmaf(v, f0.x, a[0]); a[1] = fmaf(v, f0.y, a[1]);
    a[2] = fmaf(v, f1.x, a[2]); a[3] = fmaf(v, f1.y, a[3]);
    a[4] = fmaf(v, f2.x, a[4]); a[5] = fmaf(v, f2.y, a[5]);
    a[6] = fmaf(v, f3.x, a[6]); a[7] = fmaf(v, f3.y, a[7]);
}

__device__ __forceinline__ void gather_row(const uint4* __restrict__ X, int slot,
                                           const int2* sedge, int cnt, float* a) {
    int e = 0;
    for (; e + 4 <= cnt; e += 4) {
        int2 e0 = sedge[e + 0];
        int2 e1 = sedge[e + 1];
        int2 e2 = sedge[e + 2];
        int2 e3 = sedge[e + 3];
        uint4 q0 = X[e0.x + slot];     // e.x = col*256 (uint4 row stride)
        uint4 q1 = X[e1.x + slot];
        uint4 q2 = X[e2.x + slot];
        uint4 q3 = X[e3.x + slot];
        acc8(a, q0, __int_as_float(e0.y));
        acc8(a, q1, __int_as_float(e1.y));
        acc8(a, q2, __int_as_float(e2.y));
        acc8(a, q3, __int_as_float(e3.y));
    }
    for (; e < cnt; e++) {
        int2 e0 = sedge[e];
        uint4 q = X[e0.x + slot];
        acc8(a, q, __int_as_float(e0.y));
    }
}

// Stage this block's 16x(2+64) tile (+zero pad to K=80) into A[16][88].
// y is only meaningful on owner lanes (slot%8==0).
__device__ __forceinline__ void stage_A(__half* A, int slot, const float* a, float2 y) {
    int row = (slot >> 3) & 15;
    int colb = 2 + (slot & 7) * 8;
#pragma unroll
    for (int i = 0; i < 4; i++) {
        __half2 hv = __floats2half2_rn(a[2 * i], a[2 * i + 1]);
        *(unsigned*)&A[row * 88 + colb + 2 * i] = *(unsigned*)&hv;
    }
    int r7 = slot & 7;
    if (r7 == 0) {
        __half2 hv = __floats2half2_rn(y.x, y.y);
        *(unsigned*)&A[row * 88] = *(unsigned*)&hv;
    } else if (r7 == 1) {
        unsigned* p = (unsigned*)&A[row * 88 + 66];
        p[0] = 0; p[1] = 0; p[2] = 0; p[3] = 0;      // halves 66..73
    } else if (r7 == 2) {
        unsigned* p = (unsigned*)&A[row * 88 + 74];
        p[0] = 0; p[1] = 0; p[2] = 0; p[3] = 0;      // halves 74..81 (79 is last read)
    }
}

// ---------------- pass 1: SpMM + owner-lane YI + GEMM1 + sigmoid ----------------
__global__ void __launch_bounds__(128, 8) k_spmm1f(const float* __restrict__ bias) {
    __shared__ int2   sedge[128];
    __shared__ __half A[16 * 88];
    int n = blockIdx.x >> 1;
    int h0 = blockIdx.x & 1;
    int tid = threadIdx.x;
    int slot = (h0 << 7) + tid;
    int cnt = __ldg(&g_cnt[n]);
    if (tid == 0 && h0 == 0) g_len[n] = cnt;     // snapshot for pass 2
    if (tid < cnt) sedge[tid] = g_eB[(n << 7) + tid];
    __syncthreads();

    float a[8] = {0.f, 0.f, 0.f, 0.f, 0.f, 0.f, 0.f, 0.f};
    gather_row((const uint4*)g_XSh, slot, sedge, cnt, a);

    // owner lanes: inputs-part SpMM from staged edge list (post-loop)
    float2 y = make_float2(0.f, 0.f);
    int brow = slot >> 3;
    if ((slot & 7) == 0) {
        for (int e = 0; e < cnt; e++) {
            int2 ed = sedge[e];
            float2 x = __half22float2(g_XIh[(ed.x >> 8) * 32 + brow]);
            float v = __int_as_float(ed.y);
            y.x = fmaf(v, x.x, y.x);
            y.y = fmaf(v, x.y, y.y);
        }
        g_YI[n * 32 + brow] = y;                 // for pass 2
    }
    stage_A(A, slot, a, y);
    __syncthreads();

    int lane = tid & 31, w = tid >> 5;
    int g = lane >> 2, tig = lane & 3;
    float acc[4][4] = {};
#pragma unroll
    for (int ks = 0; ks < 5; ks++) {
        int k0 = ks * 16 + 2 * tig;
        unsigned af[4];
        af[0] = *(const unsigned*)&A[g * 88 + k0];
        af[1] = *(const unsigned*)&A[(g + 8) * 88 + k0];
        af[2] = *(const unsigned*)&A[g * 88 + k0 + 8];
        af[3] = *(const unsigned*)&A[(g + 8) * 88 + k0 + 8];
#pragma unroll
        for (int nt = 0; nt < 4; nt++) {
            int nn = 32 * w + 8 * nt + g;
            unsigned bf[2];
            bf[0] = __ldg((const unsigned*)&g_wT1[nn * 88 + k0]);
            bf[1] = __ldg((const unsigned*)&g_wT1[nn * 88 + k0 + 8]);
            mma16816(acc[nt], af, bf);
        }
    }

    bool rside = (n < 5000);
#pragma unroll
    for (int nt = 0; nt < 4; nt++) {
        int j = 32 * w + 8 * nt + 2 * tig;         // output cols j, j+1
        float2 bb = *(const float2*)&bias[j];
#pragma unroll
        for (int h = 0; h < 2; h++) {
            int b = 16 * h0 + g + 8 * h;
            float v0 = sigf(acc[nt][2 * h]     + bb.x);
            float v1 = sigf(acc[nt][2 * h + 1] + bb.y);
            if (rside) {
                int t = 2 * n + (j >> 6);
                size_t off = (size_t)t * SROW + b * 64 + (j & 63);
                float2 s = __half22float2(*(const __half2*)&g_XSh[off]);
                __half2 hv = __floats2half2_rn(v0 * s.x, v1 * s.y);
                __stcs((unsigned*)&g_XS2h[off], *(unsigned*)&hv);
            } else {
                size_t off = (size_t)b * S_STRIDE + (n - 5000) * 128 + j;
                __half2 hv = __floats2half2_rn(v0, v1);
                __stcs((unsigned*)&g_Uh[off], *(unsigned*)&hv);
            }
        }
    }
}

// ---------------- pass 2: SpMM + GEMM2 + relu + GRU combine -> out ----------------
__global__ void __launch_bounds__(128, 8) k_spmm2f(const float* __restrict__ bias,
                                                   const float* __restrict__ state,
                                                   float* __restrict__ out) {
    __shared__ int2   sedge[128];
    __shared__ __half A[16 * 88];
    int n = blockIdx.x >> 1;
    int h0 = blockIdx.x & 1;
    int tid = threadIdx.x;
    int slot = (h0 << 7) + tid;
    int cnt = __ldg(&g_len[n]);
    if (tid == 0 && h0 == 0) g_cnt[n] = 0;       // clean for next replay's scatter
    if (tid < cnt) sedge[tid] = g_eB[(n << 7) + tid];
    __syncthreads();

    float a[8] = {0.f, 0.f, 0.f, 0.f, 0.f, 0.f, 0.f, 0.f};
    gather_row((const uint4*)g_XS2h, slot, sedge, cnt, a);

    float2 y = make_float2(0.f, 0.f);
    int brow = slot >> 3;
    if ((slot & 7) == 0) y = g_YI[n * 32 + brow];    // inputs-part from pass 1
    stage_A(A, slot, a, y);
    __syncthreads();

    int lane = tid & 31, w = tid >> 5;
    int g = lane >> 2, tig = lane & 3;
    float acc[2][4] = {};
#pragma unroll
    for (int ks = 0; ks < 5; ks++) {
        int k0 = ks * 16 + 2 * tig;
        unsigned af[4];
        af[0] = *(const unsigned*)&A[g * 88 + k0];
        af[1] = *(const unsigned*)&A[(g + 8) * 88 + k0];
        af[2] = *(const unsigned*)&A[g * 88 + k0 + 8];
        af[3] = *(const unsigned*)&A[(g + 8) * 88 + k0 + 8];
#pragma unroll
        for (int nt = 0; nt < 2; nt++) {
            int nn = 16 * w + 8 * nt + g;
            unsigned bf[2];
            bf[0] = __ldg((const unsigned*)&g_wT2[nn * 88 + k0]);
            bf[1] = __ldg((const unsigned*)&g_wT2[nn * 88 + k0 + 8]);
            mma16816(acc[nt], af, bf);
        }
    }

#pragma unroll
    for (int nt = 0; nt < 2; nt++) {
        int j = 16 * w + 8 * nt + 2 * tig;         // cols j, j+1 (0..63)
        float2 bb = *(const float2*)&bias[j];
#pragma unroll
        for (int h = 0; h < 2; h++) {
            int b = 16 * h0 + g + 8 * h;
            float c0 = fmaxf(acc[nt][2 * h]     + bb.x, 0.0f);
            float c1 = fmaxf(acc[nt][2 * h + 1] + bb.y, 0.0f);
            size_t off = (size_t)b * S_STRIDE + n * 64 + j;
            unsigned uu = __ldcs((const unsigned*)&g_Uh[off]);
            float2 u = __half22float2(*(__half2*)&uu);
            float2 s = *(const float2*)&state[off];
            float2 o;
            o.x = u.x * s.x + (1.0f - u.x) * c0;
            o.y = u.y * s.y + (1.0f - u.y) * c1;
            *(float2*)&out[off] = o;
        }
    }
}

// ---------------- launch ----------------
extern "C" void kernel_launch(void* const* d_in, const int* in_sizes, int n_in,
                              void* d_out, int out_size) {
    const float* inputs = (const float*)d_in[0];
    const float* state  = (const float*)d_in[1];
    const int*   m_rows = (const int*)d_in[2];
    const int*   m_cols = (const int*)d_in[3];
    const float* m_vals = (const float*)d_in[4];
    const float* w1     = (const float*)d_in[5];
    const float* b1     = (const float*)d_in[6];
    const float* w2     = (const float*)d_in[7];
    const float* b2     = (const float*)d_in[8];
    float* out = (float*)d_out;
    int nnz = in_sizes[2];

    // side: weight prep + builder, parallel with scatter
    cudaEventRecord(g_evFork, 0);
    cudaStreamWaitEvent(g_s1, g_evFork, 0);
    k_wprep<<<66, 256, 0, g_s1>>>(w1, w2);
    k_build<<<(XS_Q + N_NODES * NB + 255) / 256, 256, 0, g_s1>>>(inputs, state);
    cudaEventRecord(g_evBuild, g_s1);

    // main: bucket scatter (g_cnt is zero: .bss on first call, pass2 zeroed it last call)
    k_scatter<<<(nnz + 255) / 256, 256>>>(m_rows, m_cols, m_vals, nnz);

    // main: fused passes (need scatter [in-order] + build/wprep [event])
    cudaStreamWaitEvent(0, g_evBuild, 0);
    k_spmm1f<<<2 * N_NODES, 128>>>(b1);                 // XSh -> (XS2h, Uh, YI, len)
    k_spmm2f<<<2 * N_NODES, 128>>>(b2, state, out);     // XS2h -> out; zeroes cnt
}